// round 15
// baseline (speedup 1.0000x reference)
#include <cuda_runtime.h>

// SSIM loss: pred/target fp32 (8,8,3,256,256) -> scalar 1 - mean(ssim_map)
// 192 planes of 256x256. Depthwise 11x11 Gaussian (sigma=1.5), separable.
//
// Sum/diff basis: s = x+y, d = x-y. Four convolutions (s, d, s^2, d^2),
// computed pairwise with fma.rn.f32x2 packing (value, value^2) per stream.
//   A = conv(s), B = conv(d), S1 = conv(s^2), S2 = conv(d^2)
//   4 mu_xy = A^2 - B^2;  2(mu_x^2+mu_y^2) = A^2 + B^2
//   4 Sxy   = S1 - S2;    2(Sxx+Syy)       = S1 + S2
//
// Horizontal conv uses 8-output streaming tasks (168/stream): window loads,
// squares and packs amortize over 2x the outputs vs 4-output tasks, and
// every thread runs at most one task per stream (no straggler pass).
//
// Smem lifetime union -> 29.6 KB -> 7 blocks/SM (56 warps).
// Global reduction: fixed-point u64 RED.ADD (associative -> deterministic,
// fire-and-forget -> no per-block fence; a fence/release costs +20us here).

#define HW       256
#define PLANE    (HW * HW)
#define NPLANES  192
#define TILES_X  8
#define TILES_Y  8
#define NTHREADS 256
#define NPIX     12582912.0                       // 192*256*256
#define FXSCALE  4294967296.0                     // 2^32

#define ROWW     48                               // staged raw row width (floats)
#define NROWS    42                               // 32 out + 2*5 halo
#define RAWF     (NROWS * ROWW)                   // 2016 floats
#define PAIRF    (NROWS * 64)                     // 2688 floats (32 pairs/row)

__device__ unsigned long long g_isum = 0ULL;      // reset by finalize (replay-safe)

// Normalized Gaussian weights for ws=11, sigma=1.5.
#define GW0 0.00102838f
#define GW1 0.00759872f
#define GW2 0.03600084f
#define GW3 0.10936034f
#define GW4 0.21300566f
#define GW5 0.26601220f

typedef unsigned long long ull;

__device__ __forceinline__ void fma2(ull& d, ull a, ull b) {
    asm("fma.rn.f32x2 %0, %1, %2, %0;" : "+l"(d) : "l"(a), "l"(b));
}
__device__ __forceinline__ ull pack2(float lo, float hi) {
    ull r; asm("mov.b64 %0, {%1, %2};" : "=l"(r) : "f"(lo), "f"(hi)); return r;
}
__device__ __forceinline__ void unpack2(float& lo, float& hi, ull v) {
    asm("mov.b64 {%0, %1}, %2;" : "=f"(lo), "=f"(hi) : "l"(v));
}
__device__ __forceinline__ ull wpair(float w) {
    const unsigned u = __float_as_uint(w);
    return ((ull)u << 32) | (ull)u;
}

// Horizontal conv of one stream: raw (42x48) -> dst as (val, val^2) pairs.
// 42 rows x 4 col-groups of 8 outputs = 168 tasks (every thread <= 1 task).
// Streaming-contribution form: one float4 of the window live at a time, so
// acc[8] (16 regs) fits under the (256,7) register cap.
__device__ __forceinline__ void hconv8(
    const float* __restrict__ raw, float* __restrict__ dst,
    const int tid, const ull* __restrict__ W2)
{
    if (tid < NROWS * 4) {
        const int r  = tid >> 2;
        const int c0 = (tid & 3) * 8;
        const float* bp = &raw[r * ROWW + c0];

        // Output col c0+j (j=0..7) reads window floats [c0+3, c0+20];
        // 6 float4 chunks cover [c0, c0+23].
        ull acc[8] = {0ULL, 0ULL, 0ULL, 0ULL, 0ULL, 0ULL, 0ULL, 0ULL};
        #pragma unroll
        for (int vi = 0; vi < 6; vi++) {
            const float4 f = *reinterpret_cast<const float4*>(bp + 4 * vi);
            const float e[4] = {f.x, f.y, f.z, f.w};
            #pragma unroll
            for (int ei = 0; ei < 4; ei++) {
                const int m = 4 * vi + ei;
                if (m >= 3 && m <= 20) {
                    const float tv = e[ei];
                    const ull p = pack2(tv, tv * tv);
                    #pragma unroll
                    for (int j = 0; j < 8; j++) {
                        const int k = m - 3 - j;
                        if (k >= 0 && k <= 10)
                            fma2(acc[j], p, W2[(k < 6) ? k : 10 - k]);
                    }
                }
            }
        }
        #pragma unroll
        for (int jj = 0; jj < 4; jj++) {
            ulonglong2 st; st.x = acc[2 * jj]; st.y = acc[2 * jj + 1];
            *reinterpret_cast<ulonglong2*>(&dst[(r * 32 + c0 + 2 * jj) * 2]) = st;
        }
    }
}

__global__ __launch_bounds__(NTHREADS, 7) void ssim_main(
    const float* __restrict__ pred, const float* __restrict__ targ)
{
    __shared__ float s_rawd[RAWF];                // 8064 B: raw d tile
    // raw_s is dead once the s-stream h-conv finishes; the d-stream h-conv
    // OUTPUT (pairs) then claims this space. No read/write overlap: phase
    // A-d reads only s_rawd and writes only u.dp.
    __shared__ union {
        float raw[RAWF];                          //  8064 B: raw s tile
        float dp[PAIRF];                          // 10752 B: (convD, convD2)
    } u;
    __shared__ float s_sp[PAIRF];                 // 10752 B: (convS, convS2)
    __shared__ float s_red[8];

    const int tid = threadIdx.x;
    const int ox = blockIdx.x * 32;
    const int oy = blockIdx.y * 32;
    const int plane = blockIdx.z;
    const float* __restrict__ px = pred + (size_t)plane * PLANE;
    const float* __restrict__ py = targ + (size_t)plane * PLANE;

    ull W2[6];
    W2[0] = wpair(GW0); W2[1] = wpair(GW1); W2[2] = wpair(GW2);
    W2[3] = wpair(GW3); W2[4] = wpair(GW4); W2[5] = wpair(GW5);

    // ---- Phase 0: ONE coalesced pass stages s = x+y AND d = x-y ----
    // 42 rows x 12 float4 = 504 tasks. smem col j <-> gmem col ox-8+j.
    for (int task = tid; task < NROWS * 12; task += NTHREADS) {
        const int r  = task / 12;
        const int v  = task - r * 12;
        const int gy = oy + r - 5;
        const int gx = ox - 8 + 4 * v;

        float4 xv = make_float4(0.f, 0.f, 0.f, 0.f);
        float4 yv = xv;
        if ((unsigned)gy < (unsigned)HW && (unsigned)gx < (unsigned)HW) {
            xv = __ldg(reinterpret_cast<const float4*>(px + gy * HW + gx));
            yv = __ldg(reinterpret_cast<const float4*>(py + gy * HW + gx));
        }
        const int o = r * ROWW + 4 * v;
        *reinterpret_cast<float4*>(&u.raw[o]) =
            make_float4(xv.x + yv.x, xv.y + yv.y, xv.z + yv.z, xv.w + yv.w);
        *reinterpret_cast<float4*>(&s_rawd[o]) =
            make_float4(xv.x - yv.x, xv.y - yv.y, xv.z - yv.z, xv.w - yv.w);
    }
    __syncthreads();

    // ---- Phase A-s: h-conv of s stream (reads u.raw, writes s_sp) ----
    hconv8(u.raw, s_sp, tid, W2);
    __syncthreads();   // all reads of u.raw complete before u.dp overwrites it

    // ---- Phase A-d: h-conv of d stream (reads s_rawd, writes u.dp) ----
    hconv8(s_rawd, u.dp, tid, W2);
    __syncthreads();

    // ---- Phase B+C: packed vertical conv (4 rows) then SSIM directly ----
    // 256 tasks: tid -> (rowgroup of 4, col).
    float lsum = 0.0f;
    {
        const int rg = tid >> 5;          // 0..7
        const int c  = tid & 31;
        const int r0 = rg * 4;

        ull aS[4] = {0ULL, 0ULL, 0ULL, 0ULL};
        ull aD[4] = {0ULL, 0ULL, 0ULL, 0ULL};
        #pragma unroll
        for (int k = 0; k < 14; k++) {
            const ull vs = *reinterpret_cast<const ull*>(&s_sp[((r0 + k) * 32 + c) * 2]);
            const ull vd = *reinterpret_cast<const ull*>(&u.dp[((r0 + k) * 32 + c) * 2]);
            #pragma unroll
            for (int j = 0; j < 4; j++) {
                const int kk = k - j;
                if (kk >= 0 && kk <= 10) {
                    const int wk = (kk < 6) ? kk : 10 - kk;
                    fma2(aS[j], vs, W2[wk]);
                    fma2(aD[j], vd, W2[wk]);
                }
            }
        }

        #pragma unroll
        for (int j = 0; j < 4; j++) {
            float A, S1, B, S2;
            unpack2(A, S1, aS[j]);
            unpack2(B, S2, aD[j]);

            const float A2 = A * A;
            const float B2 = B * B;
            const float mxy  = 0.25f * (A2 - B2);          // mu_x * mu_y
            const float msum = 0.50f * (A2 + B2);          // mu_x^2 + mu_y^2
            const float sxy  = 0.25f * (S1 - S2) - mxy;    // sigma_xy
            const float ssum = fmaxf(0.50f * (S1 + S2) - msum, 0.0f);

            // den >= C1*C2 > 0 always; reference's nan_to_num is a no-op for
            // bounded inputs. Fast divide: 2^-21 rel err << 1e-3 budget.
            const float num = (2.0f * mxy + 1e-4f) * (2.0f * sxy + 9e-4f);
            const float den = (msum + 1e-4f) * (ssum + 9e-4f);
            lsum += __fdividef(num, den + 1e-8f);
        }
    }

    #pragma unroll
    for (int o = 16; o > 0; o >>= 1)
        lsum += __shfl_down_sync(0xffffffffu, lsum, o);
    if ((tid & 31) == 0) s_red[tid >> 5] = lsum;
    __syncthreads();
    if (tid == 0) {
        float v = 0.0f;
        #pragma unroll
        for (int w = 0; w < 8; w++) v += s_red[w];
        // Fixed-point RED.ADD.u64: fire-and-forget, associative, deterministic.
        atomicAdd(&g_isum, (unsigned long long)__double2ll_rn((double)v * FXSCALE));
    }
}

// Trivial finalize: one load, one store, reset accumulator for graph replay.
__global__ void ssim_finalize(float* __restrict__ out)
{
    const double s = (double)g_isum * (1.0 / FXSCALE);
    out[0] = 1.0f - (float)(s / NPIX);
    g_isum = 0ULL;
}

extern "C" void kernel_launch(void* const* d_in, const int* in_sizes, int n_in,
                              void* d_out, int out_size)
{
    const float* pred = (const float*)d_in[0];
    const float* targ = (const float*)d_in[1];
    dim3 grid(TILES_X, TILES_Y, NPLANES);
    ssim_main<<<grid, NTHREADS>>>(pred, targ);
    ssim_finalize<<<1, 1>>>((float*)d_out);
}

// round 16
// speedup vs baseline: 1.2445x; 1.2445x over previous
#include <cuda_runtime.h>

// SSIM loss: pred/target fp32 (8,8,3,256,256) -> scalar 1 - mean(ssim_map)
// 192 planes of 256x256. Depthwise 11x11 Gaussian (sigma=1.5), separable.
//
// Sum/diff basis: s = x+y, d = x-y. Four convolutions (s, d, s^2, d^2),
// computed pairwise with fma.rn.f32x2 packing (value, value^2) per stream.
//   A = conv(s), B = conv(d), S1 = conv(s^2), S2 = conv(d^2)
//   4 mu_xy = A^2 - B^2;  2(mu_x^2+mu_y^2) = A^2 + B^2
//   4 Sxy   = S1 - S2;    2(Sxx+Syy)       = S1 + S2
//
// Horizontal conv: WINDOW-RESIDENT gather form (t[20] live, acc[4]) -- the
// streaming-contribution form spills under the 36-reg cap and cost +20us in
// both R13 and R15. Do not reintroduce it.
//
// Smem lifetime union: raw_s (dead after h-conv of s) shares space with the
// d-stream's h-conv OUTPUT -> 29.6 KB total -> 7 blocks/SM (56 warps).
//
// Global reduction: fixed-point u64 RED.ADD (associative -> deterministic,
// fire-and-forget -> no per-block fence; a fence/release costs +20us here).

#define HW       256
#define PLANE    (HW * HW)
#define NPLANES  192
#define TILES_X  8
#define TILES_Y  8
#define NTHREADS 256
#define NPIX     12582912.0                       // 192*256*256
#define FXSCALE  4294967296.0                     // 2^32

#define ROWW     48                               // staged raw row width (floats)
#define NROWS    42                               // 32 out + 2*5 halo
#define RAWF     (NROWS * ROWW)                   // 2016 floats
#define PAIRF    (NROWS * 64)                     // 2688 floats (32 pairs/row)

__device__ unsigned long long g_isum = 0ULL;      // reset by finalize (replay-safe)

// Normalized Gaussian weights for ws=11, sigma=1.5.
#define GW0 0.00102838f
#define GW1 0.00759872f
#define GW2 0.03600084f
#define GW3 0.10936034f
#define GW4 0.21300566f
#define GW5 0.26601220f

typedef unsigned long long ull;

__device__ __forceinline__ void fma2(ull& d, ull a, ull b) {
    asm("fma.rn.f32x2 %0, %1, %2, %0;" : "+l"(d) : "l"(a), "l"(b));
}
__device__ __forceinline__ ull pack2(float lo, float hi) {
    ull r; asm("mov.b64 %0, {%1, %2};" : "=l"(r) : "f"(lo), "f"(hi)); return r;
}
__device__ __forceinline__ void unpack2(float& lo, float& hi, ull v) {
    asm("mov.b64 {%0, %1}, %2;" : "=f"(lo), "=f"(hi) : "l"(v));
}
__device__ __forceinline__ ull wpair(float w) {
    const unsigned u = __float_as_uint(w);
    return ((ull)u << 32) | (ull)u;
}

// Horizontal conv of one stream: raw (42x48) -> dst as (val, val^2) pairs.
// 42 rows x 8 col-groups (4 outputs) = 336 tasks. R12/R14-proven inner body.
__device__ __forceinline__ void hconv_stream(
    const float* __restrict__ raw, float* __restrict__ dst,
    const int tid, const ull* __restrict__ W2)
{
    for (int task = tid; task < NROWS * 8; task += NTHREADS) {
        const int r  = task >> 3;
        const int c0 = (task & 7) * 4;
        const float* bp = &raw[r * ROWW + c0];

        float t[20];
        #pragma unroll
        for (int vi = 0; vi < 5; vi++)
            *reinterpret_cast<float4*>(&t[4 * vi]) =
                *reinterpret_cast<const float4*>(bp + 4 * vi);

        ull acc[4] = {0ULL, 0ULL, 0ULL, 0ULL};
        #pragma unroll
        for (int m = 0; m < 14; m++) {
            const float tv = t[3 + m];
            const ull p = pack2(tv, tv * tv);
            #pragma unroll
            for (int j = 0; j < 4; j++) {
                const int k = m - j;
                if (k >= 0 && k <= 10)
                    fma2(acc[j], p, W2[(k < 6) ? k : 10 - k]);
            }
        }
        ulonglong2 st0; st0.x = acc[0]; st0.y = acc[1];
        ulonglong2 st1; st1.x = acc[2]; st1.y = acc[3];
        *reinterpret_cast<ulonglong2*>(&dst[(r * 32 + c0) * 2])     = st0;
        *reinterpret_cast<ulonglong2*>(&dst[(r * 32 + c0 + 2) * 2]) = st1;
    }
}

__global__ __launch_bounds__(NTHREADS, 7) void ssim_main(
    const float* __restrict__ pred, const float* __restrict__ targ)
{
    __shared__ float s_rawd[RAWF];                // 8064 B: raw d tile
    // raw_s is dead once the s-stream h-conv finishes; the d-stream h-conv
    // OUTPUT (pairs) then claims this space. No read/write overlap: phase
    // A-d reads only s_rawd and writes only u.dp.
    __shared__ union {
        float raw[RAWF];                          //  8064 B: raw s tile
        float dp[PAIRF];                          // 10752 B: (convD, convD2)
    } u;
    __shared__ float s_sp[PAIRF];                 // 10752 B: (convS, convS2)
    __shared__ float s_red[8];

    const int tid = threadIdx.x;
    const int ox = blockIdx.x * 32;
    const int oy = blockIdx.y * 32;
    const int plane = blockIdx.z;
    const float* __restrict__ px = pred + (size_t)plane * PLANE;
    const float* __restrict__ py = targ + (size_t)plane * PLANE;

    ull W2[6];
    W2[0] = wpair(GW0); W2[1] = wpair(GW1); W2[2] = wpair(GW2);
    W2[3] = wpair(GW3); W2[4] = wpair(GW4); W2[5] = wpair(GW5);

    // ---- Phase 0: ONE coalesced pass stages s = x+y AND d = x-y ----
    // 42 rows x 12 float4 = 504 tasks. smem col j <-> gmem col ox-8+j.
    for (int task = tid; task < NROWS * 12; task += NTHREADS) {
        const int r  = task / 12;
        const int v  = task - r * 12;
        const int gy = oy + r - 5;
        const int gx = ox - 8 + 4 * v;

        float4 xv = make_float4(0.f, 0.f, 0.f, 0.f);
        float4 yv = xv;
        if ((unsigned)gy < (unsigned)HW && (unsigned)gx < (unsigned)HW) {
            xv = __ldg(reinterpret_cast<const float4*>(px + gy * HW + gx));
            yv = __ldg(reinterpret_cast<const float4*>(py + gy * HW + gx));
        }
        const int o = r * ROWW + 4 * v;
        *reinterpret_cast<float4*>(&u.raw[o]) =
            make_float4(xv.x + yv.x, xv.y + yv.y, xv.z + yv.z, xv.w + yv.w);
        *reinterpret_cast<float4*>(&s_rawd[o]) =
            make_float4(xv.x - yv.x, xv.y - yv.y, xv.z - yv.z, xv.w - yv.w);
    }
    __syncthreads();

    // ---- Phase A-s: h-conv of s stream (reads u.raw, writes s_sp) ----
    hconv_stream(u.raw, s_sp, tid, W2);
    __syncthreads();   // all reads of u.raw complete before u.dp overwrites it

    // ---- Phase A-d: h-conv of d stream (reads s_rawd, writes u.dp) ----
    hconv_stream(s_rawd, u.dp, tid, W2);
    __syncthreads();

    // ---- Phase B+C: packed vertical conv (4 rows) then SSIM directly ----
    // 256 tasks: tid -> (rowgroup of 4, col).
    float lsum = 0.0f;
    {
        const int rg = tid >> 5;          // 0..7
        const int c  = tid & 31;
        const int r0 = rg * 4;

        ull aS[4] = {0ULL, 0ULL, 0ULL, 0ULL};
        ull aD[4] = {0ULL, 0ULL, 0ULL, 0ULL};
        #pragma unroll
        for (int k = 0; k < 14; k++) {
            const ull vs = *reinterpret_cast<const ull*>(&s_sp[((r0 + k) * 32 + c) * 2]);
            const ull vd = *reinterpret_cast<const ull*>(&u.dp[((r0 + k) * 32 + c) * 2]);
            #pragma unroll
            for (int j = 0; j < 4; j++) {
                const int kk = k - j;
                if (kk >= 0 && kk <= 10) {
                    const int wk = (kk < 6) ? kk : 10 - kk;
                    fma2(aS[j], vs, W2[wk]);
                    fma2(aD[j], vd, W2[wk]);
                }
            }
        }

        #pragma unroll
        for (int j = 0; j < 4; j++) {
            float A, S1, B, S2;
            unpack2(A, S1, aS[j]);
            unpack2(B, S2, aD[j]);

            // Folded-constant epilogue (FFMA-friendly):
            //   P  = 2*mu_xy + C1          = 0.5*A^2 - 0.5*B^2 + C1
            //   Qm = mu_x^2 + mu_y^2 + C1  = 0.5*A^2 + 0.5*B^2 + C1
            //   R  = 2*sigma_xy + C2       = 0.5*S1 - 0.5*S2 - P + C1 + C2
            //   Qs = ssum + C2             = max(0.5*S1 + 0.5*S2 - Qm + C1, 0) + C2
            const float hA = 0.5f * A;
            const float hB = 0.5f * B;
            const float P  = fmaf(hA, A, fmaf(-hB, B, 1e-4f));
            const float Qm = fmaf(hA, A, fmaf( hB, B, 1e-4f));
            const float R  = fmaf(0.5f, S1, fmaf(-0.5f, S2, 1e-4f + 9e-4f - P));
            const float Qs = fmaxf(fmaf(0.5f, S1, fmaf(0.5f, S2, 1e-4f)) - Qm, 0.0f)
                             + 9e-4f;

            // den >= C1*C2 > 0 always; reference's nan_to_num is a no-op for
            // bounded inputs. Fast divide: 2^-21 rel err << 1e-3 budget.
            lsum += __fdividef(P * R, fmaf(Qm, Qs, 1e-8f));
        }
    }

    #pragma unroll
    for (int o = 16; o > 0; o >>= 1)
        lsum += __shfl_down_sync(0xffffffffu, lsum, o);
    if ((tid & 31) == 0) s_red[tid >> 5] = lsum;
    __syncthreads();
    if (tid == 0) {
        float v = 0.0f;
        #pragma unroll
        for (int w = 0; w < 8; w++) v += s_red[w];
        // Fixed-point RED.ADD.u64: fire-and-forget, associative, deterministic.
        atomicAdd(&g_isum, (unsigned long long)__double2ll_rn((double)v * FXSCALE));
    }
}

// Trivial finalize: one load, one store, reset accumulator for graph replay.
__global__ void ssim_finalize(float* __restrict__ out)
{
    const double s = (double)g_isum * (1.0 / FXSCALE);
    out[0] = 1.0f - (float)(s / NPIX);
    g_isum = 0ULL;
}

extern "C" void kernel_launch(void* const* d_in, const int* in_sizes, int n_in,
                              void* d_out, int out_size)
{
    const float* pred = (const float*)d_in[0];
    const float* targ = (const float*)d_in[1];
    dim3 grid(TILES_X, TILES_Y, NPLANES);
    ssim_main<<<grid, NTHREADS>>>(pred, targ);
    ssim_finalize<<<1, 1>>>((float*)d_out);
}

// round 17
// speedup vs baseline: 1.2747x; 1.0243x over previous
#include <cuda_runtime.h>

// SSIM loss: pred/target fp32 (8,8,3,256,256) -> scalar 1 - mean(ssim_map)
// 192 planes of 256x256. Depthwise 11x11 Gaussian (sigma=1.5), separable.
//
// Sum/diff basis: s = x+y, d = x-y. Four convolutions (s, d, s^2, d^2),
// computed pairwise with fma.rn.f32x2 packing (value, value^2) per stream.
//   A = conv(s), B = conv(d), S1 = conv(s^2), S2 = conv(d^2)
//   4 mu_xy = A^2 - B^2;  2(mu_x^2+mu_y^2) = A^2 + B^2
//   4 Sxy   = S1 - S2;    2(Sxx+Syy)       = S1 + S2
//
// Horizontal conv: WINDOW-RESIDENT gather form (t[20] live, acc[4]) -- the
// streaming-contribution form spills under the 36-reg cap (+20us, R13/R15).
//
// Smem lifetime union: raw_s (dead after h-conv of s) shares space with the
// d-stream's h-conv OUTPUT -> 29.6 KB total -> 7 blocks/SM (56 warps).
//
// Reduction: per-thread fixed-point (2^20) -> REDUX.SUM int warp reduction
// (1 instr vs 5 SHFL+5 FADD chain) -> integer block sum -> one u64 RED.ADD
// (associative -> deterministic; fire-and-forget -> no per-block fence,
// which measured +20us at this grid).

#define HW       256
#define PLANE    (HW * HW)
#define NPLANES  192
#define TILES_X  8
#define TILES_Y  8
#define NTHREADS 256
#define NPIX     12582912.0                       // 192*256*256
#define FXSCALE  1048576.0f                       // 2^20 (per-thread fixed point)

#define ROWW     48                               // staged raw row width (floats)
#define NROWS    42                               // 32 out + 2*5 halo
#define RAWF     (NROWS * ROWW)                   // 2016 floats
#define PAIRF    (NROWS * 64)                     // 2688 floats (32 pairs/row)

__device__ unsigned long long g_isum = 0ULL;      // reset by finalize (replay-safe)

// Normalized Gaussian weights for ws=11, sigma=1.5.
#define GW0 0.00102838f
#define GW1 0.00759872f
#define GW2 0.03600084f
#define GW3 0.10936034f
#define GW4 0.21300566f
#define GW5 0.26601220f

typedef unsigned long long ull;

__device__ __forceinline__ void fma2(ull& d, ull a, ull b) {
    asm("fma.rn.f32x2 %0, %1, %2, %0;" : "+l"(d) : "l"(a), "l"(b));
}
__device__ __forceinline__ ull pack2(float lo, float hi) {
    ull r; asm("mov.b64 %0, {%1, %2};" : "=l"(r) : "f"(lo), "f"(hi)); return r;
}
__device__ __forceinline__ void unpack2(float& lo, float& hi, ull v) {
    asm("mov.b64 {%0, %1}, %2;" : "=f"(lo), "=f"(hi) : "l"(v));
}
__device__ __forceinline__ ull wpair(float w) {
    const unsigned u = __float_as_uint(w);
    return ((ull)u << 32) | (ull)u;
}

// Horizontal conv of one stream: raw (42x48) -> dst as (val, val^2) pairs.
// 42 rows x 8 col-groups (4 outputs) = 336 tasks. R12/R14-proven inner body.
__device__ __forceinline__ void hconv_stream(
    const float* __restrict__ raw, float* __restrict__ dst,
    const int tid, const ull* __restrict__ W2)
{
    for (int task = tid; task < NROWS * 8; task += NTHREADS) {
        const int r  = task >> 3;
        const int c0 = (task & 7) * 4;
        const float* bp = &raw[r * ROWW + c0];

        float t[20];
        #pragma unroll
        for (int vi = 0; vi < 5; vi++)
            *reinterpret_cast<float4*>(&t[4 * vi]) =
                *reinterpret_cast<const float4*>(bp + 4 * vi);

        ull acc[4] = {0ULL, 0ULL, 0ULL, 0ULL};
        #pragma unroll
        for (int m = 0; m < 14; m++) {
            const float tv = t[3 + m];
            const ull p = pack2(tv, tv * tv);
            #pragma unroll
            for (int j = 0; j < 4; j++) {
                const int k = m - j;
                if (k >= 0 && k <= 10)
                    fma2(acc[j], p, W2[(k < 6) ? k : 10 - k]);
            }
        }
        ulonglong2 st0; st0.x = acc[0]; st0.y = acc[1];
        ulonglong2 st1; st1.x = acc[2]; st1.y = acc[3];
        *reinterpret_cast<ulonglong2*>(&dst[(r * 32 + c0) * 2])     = st0;
        *reinterpret_cast<ulonglong2*>(&dst[(r * 32 + c0 + 2) * 2]) = st1;
    }
}

__global__ __launch_bounds__(NTHREADS, 7) void ssim_main(
    const float* __restrict__ pred, const float* __restrict__ targ)
{
    __shared__ float s_rawd[RAWF];                // 8064 B: raw d tile
    // raw_s is dead once the s-stream h-conv finishes; the d-stream h-conv
    // OUTPUT (pairs) then claims this space. No read/write overlap: phase
    // A-d reads only s_rawd and writes only u.dp.
    __shared__ union {
        float raw[RAWF];                          //  8064 B: raw s tile
        float dp[PAIRF];                          // 10752 B: (convD, convD2)
    } u;
    __shared__ float s_sp[PAIRF];                 // 10752 B: (convS, convS2)
    __shared__ int   s_redi[8];

    const int tid = threadIdx.x;
    const int ox = blockIdx.x * 32;
    const int oy = blockIdx.y * 32;
    const int plane = blockIdx.z;
    const float* __restrict__ px = pred + (size_t)plane * PLANE;
    const float* __restrict__ py = targ + (size_t)plane * PLANE;

    ull W2[6];
    W2[0] = wpair(GW0); W2[1] = wpair(GW1); W2[2] = wpair(GW2);
    W2[3] = wpair(GW3); W2[4] = wpair(GW4); W2[5] = wpair(GW5);

    // ---- Phase 0: ONE coalesced pass stages s = x+y AND d = x-y ----
    // 42 rows x 12 float4 = 504 tasks. smem col j <-> gmem col ox-8+j.
    for (int task = tid; task < NROWS * 12; task += NTHREADS) {
        const int r  = task / 12;
        const int v  = task - r * 12;
        const int gy = oy + r - 5;
        const int gx = ox - 8 + 4 * v;

        float4 xv = make_float4(0.f, 0.f, 0.f, 0.f);
        float4 yv = xv;
        if ((unsigned)gy < (unsigned)HW && (unsigned)gx < (unsigned)HW) {
            xv = __ldg(reinterpret_cast<const float4*>(px + gy * HW + gx));
            yv = __ldg(reinterpret_cast<const float4*>(py + gy * HW + gx));
        }
        const int o = r * ROWW + 4 * v;
        *reinterpret_cast<float4*>(&u.raw[o]) =
            make_float4(xv.x + yv.x, xv.y + yv.y, xv.z + yv.z, xv.w + yv.w);
        *reinterpret_cast<float4*>(&s_rawd[o]) =
            make_float4(xv.x - yv.x, xv.y - yv.y, xv.z - yv.z, xv.w - yv.w);
    }
    __syncthreads();

    // ---- Phase A-s: h-conv of s stream (reads u.raw, writes s_sp) ----
    hconv_stream(u.raw, s_sp, tid, W2);
    __syncthreads();   // all reads of u.raw complete before u.dp overwrites it

    // ---- Phase A-d: h-conv of d stream (reads s_rawd, writes u.dp) ----
    hconv_stream(s_rawd, u.dp, tid, W2);
    __syncthreads();

    // ---- Phase B+C: packed vertical conv (4 rows) then SSIM directly ----
    // 256 tasks: tid -> (rowgroup of 4, col).
    float lsum = 0.0f;
    {
        const int rg = tid >> 5;          // 0..7
        const int c  = tid & 31;
        const int r0 = rg * 4;

        ull aS[4] = {0ULL, 0ULL, 0ULL, 0ULL};
        ull aD[4] = {0ULL, 0ULL, 0ULL, 0ULL};
        #pragma unroll
        for (int k = 0; k < 14; k++) {
            const ull vs = *reinterpret_cast<const ull*>(&s_sp[((r0 + k) * 32 + c) * 2]);
            const ull vd = *reinterpret_cast<const ull*>(&u.dp[((r0 + k) * 32 + c) * 2]);
            #pragma unroll
            for (int j = 0; j < 4; j++) {
                const int kk = k - j;
                if (kk >= 0 && kk <= 10) {
                    const int wk = (kk < 6) ? kk : 10 - kk;
                    fma2(aS[j], vs, W2[wk]);
                    fma2(aD[j], vd, W2[wk]);
                }
            }
        }

        #pragma unroll
        for (int j = 0; j < 4; j++) {
            float A, S1, B, S2;
            unpack2(A, S1, aS[j]);
            unpack2(B, S2, aD[j]);

            // Folded-constant epilogue:
            //   P  = 2*mu_xy + C1          = 0.5*A^2 - 0.5*B^2 + C1
            //   Qm = mu_x^2 + mu_y^2 + C1  = 0.5*A^2 + 0.5*B^2 + C1
            //   R  = 2*sigma_xy + C2       = 0.5*S1 - 0.5*S2 - P + C1 + C2
            //   Qs = ssum + C2             = max(0.5*S1 + 0.5*S2 - Qm + C1, 0) + C2
            const float hA = 0.5f * A;
            const float hB = 0.5f * B;
            const float P  = fmaf(hA, A, fmaf(-hB, B, 1e-4f));
            const float Qm = fmaf(hA, A, fmaf( hB, B, 1e-4f));
            const float R  = fmaf(0.5f, S1, fmaf(-0.5f, S2, 1e-4f + 9e-4f - P));
            const float Qs = fmaxf(fmaf(0.5f, S1, fmaf(0.5f, S2, 1e-4f)) - Qm, 0.0f)
                             + 9e-4f;

            // den >= C1*C2 > 0 always; reference's nan_to_num is a no-op for
            // bounded inputs. Fast divide: 2^-21 rel err << 1e-3 budget.
            lsum += __fdividef(P * R, fmaf(Qm, Qs, 1e-8f));
        }
    }

    // ---- Fixed-point integer reduction: REDUX.SUM (1 instr) per warp,
    // deterministic integer adds throughout, one u64 RED per block.
    const int ilsum = __float2int_rn(lsum * FXSCALE);     // lsum <= ~4 -> fits
    const int wsum  = __reduce_add_sync(0xffffffffu, ilsum);
    if ((tid & 31) == 0) s_redi[tid >> 5] = wsum;
    __syncthreads();
    if (tid == 0) {
        long long b = 0;
        #pragma unroll
        for (int w = 0; w < 8; w++) b += (long long)s_redi[w];
        atomicAdd(&g_isum, (unsigned long long)b);
    }
}

// Trivial finalize: one load, one store, reset accumulator for graph replay.
__global__ void ssim_finalize(float* __restrict__ out)
{
    const double s = (double)(long long)g_isum * (1.0 / (double)FXSCALE);
    out[0] = 1.0f - (float)(s / NPIX);
    g_isum = 0ULL;
}

extern "C" void kernel_launch(void* const* d_in, const int* in_sizes, int n_in,
                              void* d_out, int out_size)
{
    const float* pred = (const float*)d_in[0];
    const float* targ = (const float*)d_in[1];
    dim3 grid(TILES_X, TILES_Y, NPLANES);
    ssim_main<<<grid, NTHREADS>>>(pred, targ);
    ssim_finalize<<<1, 1>>>((float*)d_out);
}